// round 4
// baseline (speedup 1.0000x reference)
#include <cuda_runtime.h>
#include <stdint.h>

#define NNODES 40000
#define NEDGES 640000
#define NGRAPH 64
#define DIN    128
#define DH     256
#define DOUTC  128

#define SCAN_B 256
#define SCAN_NB ((NNODES + SCAN_B - 1) / SCAN_B)   // 157

// ---- scratch (no allocations allowed) ----
__device__ float g_bufA[NNODES * DH];
__device__ float g_bufB[NNODES * DH];
__device__ float g_dis[NNODES];
__device__ float g_cnt[NGRAPH];
// CSR scratch
__device__ int   g_cnti[NNODES];
__device__ int   g_rowptr[NNODES + 1];
__device__ int   g_cursor[NNODES];
__device__ int   g_esrc[NEDGES];
__device__ float g_ecoef[NEDGES];
__device__ int   g_bsum[SCAN_NB];
__device__ int   g_bpre[SCAN_NB];

// ---------------------------------------------------------------------------
// packed fp32x2 fma
// ---------------------------------------------------------------------------
__device__ __forceinline__ void fma2(unsigned long long& d, unsigned long long a,
                                     unsigned long long b) {
    asm("fma.rn.f32x2 %0, %1, %2, %0;" : "+l"(d) : "l"(a), "l"(b));
}
__device__ __forceinline__ float2 unpack2(unsigned long long v) {
    float2 r;
    asm("mov.b64 {%0, %1}, %2;" : "=f"(r.x), "=f"(r.y) : "l"(v));
    return r;
}

// ---------------------------------------------------------------------------
// small utility kernels
// ---------------------------------------------------------------------------
__global__ void fill_kernel(float4* __restrict__ p, float v, int n4) {
    int i = blockIdx.x * blockDim.x + threadIdx.x;
    float4 f = make_float4(v, v, v, v);
    for (; i < n4; i += gridDim.x * blockDim.x) p[i] = f;
}

__global__ void zeroi_kernel(int* __restrict__ p, int n) {
    int i = blockIdx.x * blockDim.x + threadIdx.x;
    if (i < n) p[i] = 0;
}

__global__ void hist_kernel(const int* __restrict__ dst, int E) {
    int e = blockIdx.x * blockDim.x + threadIdx.x;
    if (e < E) atomicAdd(&g_cnti[dst[e]], 1);
}

__global__ void dis_kernel(int n) {
    int i = blockIdx.x * blockDim.x + threadIdx.x;
    if (i < n) g_dis[i] = rsqrtf((float)g_cnti[i] + 1.0f);
}

// ---------------------------------------------------------------------------
// three-phase scan of g_cnti -> g_rowptr / g_cursor
// ---------------------------------------------------------------------------
__global__ void scan1_kernel() {
    __shared__ int s[SCAN_B];
    int i = blockIdx.x * SCAN_B + threadIdx.x;
    s[threadIdx.x] = (i < NNODES) ? g_cnti[i] : 0;
    __syncthreads();
    for (int off = SCAN_B / 2; off > 0; off >>= 1) {
        if (threadIdx.x < off) s[threadIdx.x] += s[threadIdx.x + off];
        __syncthreads();
    }
    if (threadIdx.x == 0) g_bsum[blockIdx.x] = s[0];
}

__global__ void scan2_kernel() {
    __shared__ int s[SCAN_NB];
    int t = threadIdx.x;
    if (t < SCAN_NB) s[t] = g_bsum[t];
    __syncthreads();
    for (int off = 1; off < SCAN_NB; off <<= 1) {
        int v = 0;
        if (t < SCAN_NB && t >= off) v = s[t - off];
        __syncthreads();
        if (t < SCAN_NB && t >= off) s[t] += v;
        __syncthreads();
    }
    if (t < SCAN_NB) g_bpre[t] = (t == 0) ? 0 : s[t - 1];
    if (t == 0) g_rowptr[NNODES] = NEDGES;
}

__global__ void scan3_kernel() {
    __shared__ int s[SCAN_B];
    int i = blockIdx.x * SCAN_B + threadIdx.x;
    int t = threadIdx.x;
    int v0 = (i < NNODES) ? g_cnti[i] : 0;
    s[t] = v0;
    __syncthreads();
    for (int off = 1; off < SCAN_B; off <<= 1) {
        int v = (t >= off) ? s[t - off] : 0;
        __syncthreads();
        s[t] += v;
        __syncthreads();
    }
    if (i < NNODES) {
        int ex = g_bpre[blockIdx.x] + s[t] - v0;
        g_rowptr[i] = ex;
        g_cursor[i] = ex;
    }
}

__global__ void csrfill_kernel(const int* __restrict__ src, const int* __restrict__ dst,
                               int E) {
    int e = blockIdx.x * blockDim.x + threadIdx.x;
    if (e >= E) return;
    int s = src[e], d = dst[e];
    int p = atomicAdd(&g_cursor[d], 1);
    g_esrc[p]  = s;
    g_ecoef[p] = g_dis[s] * g_dis[d];
}

// ---------------------------------------------------------------------------
// fp32 tiled GEMM with packed f32x2 FMAs: C[N,M] = A[N,K] @ B[K,M]
// block (16,16)=256 thr, tile 128x64, K-tile 16, 8x4 per thread.
// Row-pairs packed in 64-bit lanes; B stored duplicated (b,b) in shared.
// ---------------------------------------------------------------------------
__global__ void __launch_bounds__(256)
gemm_kernel(const float* __restrict__ A, const float* __restrict__ B,
            float* __restrict__ C, int N, int K, int M) {
    __shared__ float As[16][128];
    __shared__ float Bs2[16][128];   // duplicated: col j at [2j](=b) and [2j+1](=b)
    const int tid = threadIdx.y * 16 + threadIdx.x;
    const int rowBase = blockIdx.y * 128;
    const int colBase = blockIdx.x * 64;

    unsigned long long acc2[4][4] = {};   // [row-pair][col]

    for (int k0 = 0; k0 < K; k0 += 16) {
        #pragma unroll
        for (int l = 0; l < 2; ++l) {       // A tile: 128 rows x 16 k, transposed
            int idx = tid + l * 256;
            int r   = idx >> 2;
            int kk  = (idx & 3) * 4;
            int rr  = min(rowBase + r, N - 1);
            float4 v = *(const float4*)(A + (size_t)rr * K + k0 + kk);
            As[kk + 0][r] = v.x; As[kk + 1][r] = v.y;
            As[kk + 2][r] = v.z; As[kk + 3][r] = v.w;
        }
        {   // B tile: 16 k x 64 cols, stored duplicated
            int kr = tid >> 4;
            int cc = (tid & 15) * 4;
            float4 v = *(const float4*)(B + (size_t)(k0 + kr) * M + colBase + cc);
            float4 d0 = make_float4(v.x, v.x, v.y, v.y);
            float4 d1 = make_float4(v.z, v.z, v.w, v.w);
            *(float4*)&Bs2[kr][cc * 2]     = d0;
            *(float4*)&Bs2[kr][cc * 2 + 4] = d1;
        }
        __syncthreads();
        #pragma unroll
        for (int kk = 0; kk < 16; ++kk) {
            // a row-pairs: 8 consecutive floats = 4 packed pairs
            ulonglong2 a01 = *(ulonglong2*)&As[kk][threadIdx.y * 8];
            ulonglong2 a23 = *(ulonglong2*)&As[kk][threadIdx.y * 8 + 4];
            // b duplicated pairs: (b0,b0),(b1,b1),(b2,b2),(b3,b3)
            ulonglong2 b01 = *(ulonglong2*)&Bs2[kk][threadIdx.x * 8];
            ulonglong2 b23 = *(ulonglong2*)&Bs2[kk][threadIdx.x * 8 + 4];
            unsigned long long ap[4] = {a01.x, a01.y, a23.x, a23.y};
            unsigned long long bp[4] = {b01.x, b01.y, b23.x, b23.y};
            #pragma unroll
            for (int i = 0; i < 4; ++i)
                #pragma unroll
                for (int j = 0; j < 4; ++j) fma2(acc2[i][j], ap[i], bp[j]);
        }
        __syncthreads();
    }
    #pragma unroll
    for (int i2 = 0; i2 < 4; ++i2) {
        float2 c0 = unpack2(acc2[i2][0]);
        float2 c1 = unpack2(acc2[i2][1]);
        float2 c2 = unpack2(acc2[i2][2]);
        float2 c3 = unpack2(acc2[i2][3]);
        int r0 = rowBase + threadIdx.y * 8 + i2 * 2;
        if (r0 < N) {
            float4 o = make_float4(c0.x, c1.x, c2.x, c3.x);
            *(float4*)(C + (size_t)r0 * M + colBase + threadIdx.x * 4) = o;
        }
        if (r0 + 1 < N) {
            float4 o = make_float4(c0.y, c1.y, c2.y, c3.y);
            *(float4*)(C + (size_t)(r0 + 1) * M + colBase + threadIdx.x * 4) = o;
        }
    }
}

// ---------------------------------------------------------------------------
// fused gather + self-loop + bias (+relu)
// ---------------------------------------------------------------------------
template <int H, bool RELU>
__global__ void gather_kernel(const float* __restrict__ h, const float* __restrict__ bias,
                              float* __restrict__ out) {
    constexpr int HALVES = H / 128;
    int w = (blockIdx.x * blockDim.x + threadIdx.x) >> 5;
    int n = w / HALVES;
    if (n >= NNODES) return;
    int half = w - n * HALVES;
    int lane = threadIdx.x & 31;
    int col  = half * 128 + lane * 4;

    int p  = g_rowptr[n];
    int p1 = g_rowptr[n + 1];

    float4 acc = make_float4(0.f, 0.f, 0.f, 0.f);
    for (; p + 3 < p1; p += 4) {
        int   s0 = g_esrc[p],  s1 = g_esrc[p + 1];
        int   s2 = g_esrc[p + 2], s3 = g_esrc[p + 3];
        float c0 = g_ecoef[p], c1 = g_ecoef[p + 1];
        float c2 = g_ecoef[p + 2], c3 = g_ecoef[p + 3];
        float4 v0 = __ldg((const float4*)(h + (size_t)s0 * H + col));
        float4 v1 = __ldg((const float4*)(h + (size_t)s1 * H + col));
        float4 v2 = __ldg((const float4*)(h + (size_t)s2 * H + col));
        float4 v3 = __ldg((const float4*)(h + (size_t)s3 * H + col));
        acc.x += c0 * v0.x + c1 * v1.x + c2 * v2.x + c3 * v3.x;
        acc.y += c0 * v0.y + c1 * v1.y + c2 * v2.y + c3 * v3.y;
        acc.z += c0 * v0.z + c1 * v1.z + c2 * v2.z + c3 * v3.z;
        acc.w += c0 * v0.w + c1 * v1.w + c2 * v2.w + c3 * v3.w;
    }
    for (; p < p1; ++p) {
        int s = g_esrc[p]; float c = g_ecoef[p];
        float4 v = __ldg((const float4*)(h + (size_t)s * H + col));
        acc.x += c * v.x; acc.y += c * v.y; acc.z += c * v.z; acc.w += c * v.w;
    }

    float dis = g_dis[n];
    float c2 = dis * dis;
    float4 hv = __ldg((const float4*)(h + (size_t)n * H + col));
    float4 bv = __ldg((const float4*)(bias + col));
    float4 r;
    r.x = acc.x + c2 * hv.x + bv.x;
    r.y = acc.y + c2 * hv.y + bv.y;
    r.z = acc.z + c2 * hv.z + bv.z;
    r.w = acc.w + c2 * hv.w + bv.w;
    if (RELU) {
        r.x = fmaxf(r.x, 0.f); r.y = fmaxf(r.y, 0.f);
        r.z = fmaxf(r.z, 0.f); r.w = fmaxf(r.w, 0.f);
    }
    *(float4*)(out + (size_t)n * H + col) = r;
}

// ---------------------------------------------------------------------------
// pooling + classifier
// ---------------------------------------------------------------------------
__global__ void pool_kernel(const float* __restrict__ ne, const int* __restrict__ batch,
                            float* __restrict__ gsum, int N) {
    int c  = threadIdx.x;
    int n0 = blockIdx.x * 256;
    int n1 = min(n0 + 256, N);
    float acc = 0.0f;
    int cur = -1;
    for (int n = n0; n < n1; ++n) {
        int g = __ldg(&batch[n]);
        if (g != cur) {
            if (cur >= 0) atomicAdd(&gsum[cur * DOUTC + c], acc);
            acc = 0.0f;
            cur = g;
        }
        acc += ne[(size_t)n * DOUTC + c];
    }
    if (cur >= 0) atomicAdd(&gsum[cur * DOUTC + c], acc);
}

__global__ void counts_kernel(const int* __restrict__ batch, int N) {
    __shared__ float s[NGRAPH];
    if (threadIdx.x < NGRAPH) s[threadIdx.x] = 0.0f;
    __syncthreads();
    for (int n = blockIdx.x * blockDim.x + threadIdx.x; n < N;
         n += gridDim.x * blockDim.x)
        atomicAdd(&s[batch[n]], 1.0f);
    __syncthreads();
    if (threadIdx.x < NGRAPH && s[threadIdx.x] > 0.0f)
        atomicAdd(&g_cnt[threadIdx.x], s[threadIdx.x]);
}

__global__ void gdiv_kernel(float* __restrict__ gsum) {
    int i = blockIdx.x * blockDim.x + threadIdx.x;
    if (i < NGRAPH * DOUTC) {
        int g = i / DOUTC;
        gsum[i] = gsum[i] / fmaxf(g_cnt[g], 1.0f);
    }
}

__global__ void logits_kernel(const float* __restrict__ ge, const float* __restrict__ Wc,
                              const float* __restrict__ bc, float* __restrict__ out) {
    int t = threadIdx.x;
    int g = t >> 1, j = t & 1;
    float s = __ldg(&bc[j]);
    #pragma unroll 8
    for (int c = 0; c < DOUTC; ++c)
        s += ge[g * DOUTC + c] * __ldg(&Wc[c * 2 + j]);
    out[t] = s;
}

// ---------------------------------------------------------------------------
// launch
// ---------------------------------------------------------------------------
extern "C" void kernel_launch(void* const* d_in, const int* in_sizes, int n_in,
                              void* d_out, int out_size) {
    const float* x     = (const float*)d_in[0];
    const int*   ei    = (const int*)d_in[1];
    const int*   batch = (const int*)d_in[2];
    const float* W_in  = (const float*)d_in[3];
    const float* b_in  = (const float*)d_in[4];
    const float* W_mid = (const float*)d_in[5];
    const float* b_mid = (const float*)d_in[6];
    const float* W_out = (const float*)d_in[7];
    const float* b_out = (const float*)d_in[8];
    const float* W_cls = (const float*)d_in[9];
    const float* b_cls = (const float*)d_in[10];

    const int* src = ei;
    const int* dst = ei + NEDGES;

    float *bufA, *bufB, *cntp;
    int *cnti;
    cudaGetSymbolAddress((void**)&bufA, g_bufA);
    cudaGetSymbolAddress((void**)&bufB, g_bufB);
    cudaGetSymbolAddress((void**)&cntp, g_cnt);
    cudaGetSymbolAddress((void**)&cnti, g_cnti);

    float* node   = (float*)d_out;
    float* gsum   = node + (size_t)NNODES * DOUTC;
    float* logit  = gsum + NGRAPH * DOUTC;

    const int T = 256;

    // ----- CSR build + norm coefficients -----
    zeroi_kernel<<<(NNODES + T - 1) / T, T>>>(cnti, NNODES);
    hist_kernel<<<(NEDGES + T - 1) / T, T>>>(dst, NEDGES);
    dis_kernel<<<(NNODES + T - 1) / T, T>>>(NNODES);
    scan1_kernel<<<SCAN_NB, SCAN_B>>>();
    scan2_kernel<<<1, SCAN_B>>>();
    scan3_kernel<<<SCAN_NB, SCAN_B>>>();
    csrfill_kernel<<<(NEDGES + T - 1) / T, T>>>(src, dst, NEDGES);

    // ----- layer 1 -----
    gemm_kernel<<<dim3(DH / 64, (NNODES + 127) / 128), dim3(16, 16)>>>(x, W_in, bufA,
                                                                       NNODES, DIN, DH);
    gather_kernel<DH, true><<<(NNODES * 2 * 32 + T - 1) / T, T>>>(bufA, b_in, bufB);

    // ----- layer 2 -----
    gemm_kernel<<<dim3(DH / 64, (NNODES + 127) / 128), dim3(16, 16)>>>(bufB, W_mid, bufA,
                                                                       NNODES, DH, DH);
    gather_kernel<DH, true><<<(NNODES * 2 * 32 + T - 1) / T, T>>>(bufA, b_mid, bufB);

    // ----- layer 3 -----
    gemm_kernel<<<dim3(DOUTC / 64, (NNODES + 127) / 128), dim3(16, 16)>>>(bufB, W_out, bufA,
                                                                          NNODES, DH, DOUTC);
    gather_kernel<DOUTC, false><<<(NNODES * 1 * 32 + T - 1) / T, T>>>(bufA, b_out, node);

    // ----- mean pool + classifier -----
    fill_kernel<<<8, T>>>((float4*)gsum, 0.0f, NGRAPH * DOUTC / 4);
    fill_kernel<<<1, 16>>>((float4*)cntp, 0.0f, NGRAPH / 4);
    counts_kernel<<<64, T>>>(batch, NNODES);
    pool_kernel<<<(NNODES + 255) / 256, 128>>>(node, batch, gsum, NNODES);
    gdiv_kernel<<<(NGRAPH * DOUTC + T - 1) / T, T>>>(gsum);
    logits_kernel<<<1, 128>>>(gsum, W_cls, b_cls, logit);
}

// round 6
// speedup vs baseline: 1.6656x; 1.6656x over previous
#include <cuda_runtime.h>
#include <cuda_bf16.h>
#include <stdint.h>

#define NNODES 40000
#define NEDGES 640000
#define NGRAPH 64
#define DIN    128
#define DH     256
#define DOUTC  128

#define SCAN_B 256
#define SCAN_NB ((NNODES + SCAN_B - 1) / SCAN_B)   // 157

// ---- scratch (no allocations allowed) ----
__device__ float g_bufA[NNODES * DH];
__device__ float g_bufB[NNODES * DH];
__device__ float g_dis[NNODES];
__device__ float g_cnt[NGRAPH];
// CSR scratch
__device__ int   g_cnti[NNODES];
__device__ int   g_rowptr[NNODES + 1];
__device__ int   g_cursor[NNODES];
__device__ int   g_esrc[NEDGES];
__device__ float g_ecoef[NEDGES];
__device__ int   g_bsum[SCAN_NB];
__device__ int   g_bpre[SCAN_NB];
// weights transposed to [NOUT, K] row-major, bf16 hi/lo split
__device__ __nv_bfloat16 g_w1_hi[DH * DIN];
__device__ __nv_bfloat16 g_w1_lo[DH * DIN];
__device__ __nv_bfloat16 g_w2_hi[DH * DH];
__device__ __nv_bfloat16 g_w2_lo[DH * DH];
__device__ __nv_bfloat16 g_w3_hi[DOUTC * DH];
__device__ __nv_bfloat16 g_w3_lo[DOUTC * DH];

// ---------------------------------------------------------------------------
// small utility kernels
// ---------------------------------------------------------------------------
__global__ void fill_kernel(float4* __restrict__ p, float v, int n4) {
    int i = blockIdx.x * blockDim.x + threadIdx.x;
    float4 f = make_float4(v, v, v, v);
    for (; i < n4; i += gridDim.x * blockDim.x) p[i] = f;
}

__global__ void zeroi_kernel(int* __restrict__ p, int n) {
    int i = blockIdx.x * blockDim.x + threadIdx.x;
    if (i < n) p[i] = 0;
}

__global__ void hist_kernel(const int* __restrict__ dst, int E) {
    int e = blockIdx.x * blockDim.x + threadIdx.x;
    if (e < E) atomicAdd(&g_cnti[dst[e]], 1);
}

__global__ void dis_kernel(int n) {
    int i = blockIdx.x * blockDim.x + threadIdx.x;
    if (i < n) g_dis[i] = rsqrtf((float)g_cnti[i] + 1.0f);
}

// weight prep: W[K, NOUT] fp32 -> transposed [NOUT, K], bf16 hi/lo split
__global__ void wprep_kernel(const float* __restrict__ W, __nv_bfloat16* __restrict__ hi,
                             __nv_bfloat16* __restrict__ lo, int K, int NOUT) {
    int idx = blockIdx.x * blockDim.x + threadIdx.x;
    if (idx >= K * NOUT) return;
    int k = idx / NOUT, n = idx - k * NOUT;
    float v = W[idx];
    __nv_bfloat16 h = __float2bfloat16(v);
    __nv_bfloat16 l = __float2bfloat16(v - __bfloat162float(h));
    hi[(size_t)n * K + k] = h;
    lo[(size_t)n * K + k] = l;
}

// ---------------------------------------------------------------------------
// three-phase scan of g_cnti -> g_rowptr / g_cursor
// ---------------------------------------------------------------------------
__global__ void scan1_kernel() {
    __shared__ int s[SCAN_B];
    int i = blockIdx.x * SCAN_B + threadIdx.x;
    s[threadIdx.x] = (i < NNODES) ? g_cnti[i] : 0;
    __syncthreads();
    for (int off = SCAN_B / 2; off > 0; off >>= 1) {
        if (threadIdx.x < off) s[threadIdx.x] += s[threadIdx.x + off];
        __syncthreads();
    }
    if (threadIdx.x == 0) g_bsum[blockIdx.x] = s[0];
}

__global__ void scan2_kernel() {
    __shared__ int s[SCAN_NB];
    int t = threadIdx.x;
    if (t < SCAN_NB) s[t] = g_bsum[t];
    __syncthreads();
    for (int off = 1; off < SCAN_NB; off <<= 1) {
        int v = 0;
        if (t < SCAN_NB && t >= off) v = s[t - off];
        __syncthreads();
        if (t < SCAN_NB && t >= off) s[t] += v;
        __syncthreads();
    }
    if (t < SCAN_NB) g_bpre[t] = (t == 0) ? 0 : s[t - 1];
    if (t == 0) g_rowptr[NNODES] = NEDGES;
}

__global__ void scan3_kernel() {
    __shared__ int s[SCAN_B];
    int i = blockIdx.x * SCAN_B + threadIdx.x;
    int t = threadIdx.x;
    int v0 = (i < NNODES) ? g_cnti[i] : 0;
    s[t] = v0;
    __syncthreads();
    for (int off = 1; off < SCAN_B; off <<= 1) {
        int v = (t >= off) ? s[t - off] : 0;
        __syncthreads();
        s[t] += v;
        __syncthreads();
    }
    if (i < NNODES) {
        int ex = g_bpre[blockIdx.x] + s[t] - v0;
        g_rowptr[i] = ex;
        g_cursor[i] = ex;
    }
}

__global__ void csrfill_kernel(const int* __restrict__ src, const int* __restrict__ dst,
                               int E) {
    int e = blockIdx.x * blockDim.x + threadIdx.x;
    if (e >= E) return;
    int s = src[e], d = dst[e];
    int p = atomicAdd(&g_cursor[d], 1);
    g_esrc[p]  = s;
    g_ecoef[p] = g_dis[s] * g_dis[d];
}

// ---------------------------------------------------------------------------
// 3xBF16 split GEMM via mma.sync.m16n8k16: C[N, NOUT] = A[N, K] @ W[K, NOUT]
// CTA: 512 thr, output tile 128x128, K-step 32. Warp grid 4x4, warp tile 32x32.
// A fp32 -> hi/lo bf16 in smem; W pre-split, [NOUT, K] row-major ("col" operand).
// ---------------------------------------------------------------------------
__device__ __forceinline__ void mma16816(float* c, const uint32_t* a, const uint32_t* b) {
    asm volatile(
        "mma.sync.aligned.m16n8k16.row.col.f32.bf16.bf16.f32 "
        "{%0,%1,%2,%3}, {%4,%5,%6,%7}, {%8,%9}, {%0,%1,%2,%3};"
        : "+f"(c[0]), "+f"(c[1]), "+f"(c[2]), "+f"(c[3])
        : "r"(a[0]), "r"(a[1]), "r"(a[2]), "r"(a[3]), "r"(b[0]), "r"(b[1]));
}

template <int K>
__global__ void __launch_bounds__(512)
mma_gemm_kernel(const float* __restrict__ A, const __nv_bfloat16* __restrict__ Whi,
                const __nv_bfloat16* __restrict__ Wlo, float* __restrict__ C,
                int N, int NOUT) {
    __shared__ __nv_bfloat16 AsH[128][40];   // 32 k + 8 pad (conflict-free frags)
    __shared__ __nv_bfloat16 AsL[128][40];
    __shared__ __nv_bfloat16 BsH[128][40];
    __shared__ __nv_bfloat16 BsL[128][40];

    const int tid = threadIdx.x;
    const int wid = tid >> 5, lane = tid & 31;
    const int mw = (wid & 3) * 32;        // warp row offset in tile
    const int nw = (wid >> 2) * 32;       // warp col offset in tile
    const int m0 = blockIdx.y * 128;
    const int n0 = blockIdx.x * 128;

    float acc[2][4][4] = {};              // [mtile][ntile][reg]

    const int ar = lane >> 2;             // 0..7
    const int ac = (lane & 3) * 2;        // 0,2,4,6

    for (int kt = 0; kt < K; kt += 32) {
        // ---- stage A: 128 rows x 32 k, fp32 -> hi/lo bf16 ----
        #pragma unroll
        for (int it = 0; it < 4; ++it) {
            int idx = tid + it * 512;     // 2048 float2 slots
            int r  = idx >> 4;
            int kp = (idx & 15) * 2;
            int rr = min(m0 + r, N - 1);
            float2 v = *(const float2*)(A + (size_t)rr * K + kt + kp);
            __nv_bfloat16 h0 = __float2bfloat16(v.x);
            __nv_bfloat16 h1 = __float2bfloat16(v.y);
            __nv_bfloat16 l0 = __float2bfloat16(v.x - __bfloat162float(h0));
            __nv_bfloat16 l1 = __float2bfloat16(v.y - __bfloat162float(h1));
            uint32_t hp = (uint32_t)__bfloat16_as_ushort(h0) |
                          ((uint32_t)__bfloat16_as_ushort(h1) << 16);
            uint32_t lp = (uint32_t)__bfloat16_as_ushort(l0) |
                          ((uint32_t)__bfloat16_as_ushort(l1) << 16);
            *(uint32_t*)&AsH[r][kp] = hp;
            *(uint32_t*)&AsL[r][kp] = lp;
        }
        // ---- stage B: 128 n-rows x 32 k from [NOUT, K] bf16, 16B per thread ----
        {
            int r = tid >> 2;
            int c = (tid & 3) * 8;
            uint4 vh = *(const uint4*)(Whi + (size_t)(n0 + r) * K + kt + c);
            uint4 vl = *(const uint4*)(Wlo + (size_t)(n0 + r) * K + kt + c);
            *(uint4*)&BsH[r][c] = vh;
            *(uint4*)&BsL[r][c] = vl;
        }
        __syncthreads();

        #pragma unroll
        for (int k16 = 0; k16 < 32; k16 += 16) {
            uint32_t ah[2][4], al[2][4];
            #pragma unroll
            for (int mt = 0; mt < 2; ++mt) {
                int r = mw + mt * 16 + ar;
                ah[mt][0] = *(uint32_t*)&AsH[r][k16 + ac];
                ah[mt][1] = *(uint32_t*)&AsH[r + 8][k16 + ac];
                ah[mt][2] = *(uint32_t*)&AsH[r][k16 + ac + 8];
                ah[mt][3] = *(uint32_t*)&AsH[r + 8][k16 + ac + 8];
                al[mt][0] = *(uint32_t*)&AsL[r][k16 + ac];
                al[mt][1] = *(uint32_t*)&AsL[r + 8][k16 + ac];
                al[mt][2] = *(uint32_t*)&AsL[r][k16 + ac + 8];
                al[mt][3] = *(uint32_t*)&AsL[r + 8][k16 + ac + 8];
            }
            uint32_t bh[4][2], bl[4][2];
            #pragma unroll
            for (int nt = 0; nt < 4; ++nt) {
                int r = nw + nt * 8 + ar;
                bh[nt][0] = *(uint32_t*)&BsH[r][k16 + ac];
                bh[nt][1] = *(uint32_t*)&BsH[r][k16 + ac + 8];
                bl[nt][0] = *(uint32_t*)&BsL[r][k16 + ac];
                bl[nt][1] = *(uint32_t*)&BsL[r][k16 + ac + 8];
            }
            #pragma unroll
            for (int mt = 0; mt < 2; ++mt)
                #pragma unroll
                for (int nt = 0; nt < 4; ++nt) {
                    mma16816(acc[mt][nt], ah[mt], bh[nt]);
                    mma16816(acc[mt][nt], ah[mt], bl[nt]);
                    mma16816(acc[mt][nt], al[mt], bh[nt]);
                }
        }
        __syncthreads();
    }

    // ---- store: c0,c1 at (row, col..col+1), c2,c3 at (row+8, ...) ----
    #pragma unroll
    for (int mt = 0; mt < 2; ++mt) {
        int r0 = m0 + mw + mt * 16 + ar;
        #pragma unroll
        for (int nt = 0; nt < 4; ++nt) {
            int c = n0 + nw + nt * 8 + ac;
            if (r0 < N)
                *(float2*)(C + (size_t)r0 * NOUT + c) =
                    make_float2(acc[mt][nt][0], acc[mt][nt][1]);
            if (r0 + 8 < N)
                *(float2*)(C + (size_t)(r0 + 8) * NOUT + c) =
                    make_float2(acc[mt][nt][2], acc[mt][nt][3]);
        }
    }
}

// ---------------------------------------------------------------------------
// fused gather + self-loop + bias (+relu)
// ---------------------------------------------------------------------------
template <int H, bool RELU>
__global__ void gather_kernel(const float* __restrict__ h, const float* __restrict__ bias,
                              float* __restrict__ out) {
    constexpr int HALVES = H / 128;
    int w = (blockIdx.x * blockDim.x + threadIdx.x) >> 5;
    int n = w / HALVES;
    if (n >= NNODES) return;
    int half = w - n * HALVES;
    int lane = threadIdx.x & 31;
    int col  = half * 128 + lane * 4;

    int p  = g_rowptr[n];
    int p1 = g_rowptr[n + 1];

    float4 acc = make_float4(0.f, 0.f, 0.f, 0.f);
    for (; p + 3 < p1; p += 4) {
        int   s0 = g_esrc[p],     s1 = g_esrc[p + 1];
        int   s2 = g_esrc[p + 2], s3 = g_esrc[p + 3];
        float c0 = g_ecoef[p],     c1 = g_ecoef[p + 1];
        float c2 = g_ecoef[p + 2], c3 = g_ecoef[p + 3];
        float4 v0 = __ldg((const float4*)(h + (size_t)s0 * H + col));
        float4 v1 = __ldg((const float4*)(h + (size_t)s1 * H + col));
        float4 v2 = __ldg((const float4*)(h + (size_t)s2 * H + col));
        float4 v3 = __ldg((const float4*)(h + (size_t)s3 * H + col));
        acc.x += c0 * v0.x + c1 * v1.x + c2 * v2.x + c3 * v3.x;
        acc.y += c0 * v0.y + c1 * v1.y + c2 * v2.y + c3 * v3.y;
        acc.z += c0 * v0.z + c1 * v1.z + c2 * v2.z + c3 * v3.z;
        acc.w += c0 * v0.w + c1 * v1.w + c2 * v2.w + c3 * v3.w;
    }
    for (; p < p1; ++p) {
        int s = g_esrc[p]; float c = g_ecoef[p];
        float4 v = __ldg((const float4*)(h + (size_t)s * H + col));
        acc.x += c * v.x; acc.y += c * v.y; acc.z += c * v.z; acc.w += c * v.w;
    }

    float dis = g_dis[n];
    float c2 = dis * dis;
    float4 hv = __ldg((const float4*)(h + (size_t)n * H + col));
    float4 bv = __ldg((const float4*)(bias + col));
    float4 r;
    r.x = acc.x + c2 * hv.x + bv.x;
    r.y = acc.y + c2 * hv.y + bv.y;
    r.z = acc.z + c2 * hv.z + bv.z;
    r.w = acc.w + c2 * hv.w + bv.w;
    if (RELU) {
        r.x = fmaxf(r.x, 0.f); r.y = fmaxf(r.y, 0.f);
        r.z = fmaxf(r.z, 0.f); r.w = fmaxf(r.w, 0.f);
    }
    *(float4*)(out + (size_t)n * H + col) = r;
}

// ---------------------------------------------------------------------------
// pooling + classifier
// ---------------------------------------------------------------------------
__global__ void pool_kernel(const float* __restrict__ ne, const int* __restrict__ batch,
                            float* __restrict__ gsum, int N) {
    int c  = threadIdx.x;
    int n0 = blockIdx.x * 256;
    int n1 = min(n0 + 256, N);
    float acc = 0.0f;
    int cur = -1;
    for (int n = n0; n < n1; ++n) {
        int g = __ldg(&batch[n]);
        if (g != cur) {
            if (cur >= 0) atomicAdd(&gsum[cur * DOUTC + c], acc);
            acc = 0.0f;
            cur = g;
        }
        acc += ne[(size_t)n * DOUTC + c];
    }
    if (cur >= 0) atomicAdd(&gsum[cur * DOUTC + c], acc);
}

__global__ void counts_kernel(const int* __restrict__ batch, int N) {
    __shared__ float s[NGRAPH];
    if (threadIdx.x < NGRAPH) s[threadIdx.x] = 0.0f;
    __syncthreads();
    for (int n = blockIdx.x * blockDim.x + threadIdx.x; n < N;
         n += gridDim.x * blockDim.x)
        atomicAdd(&s[batch[n]], 1.0f);
    __syncthreads();
    if (threadIdx.x < NGRAPH && s[threadIdx.x] > 0.0f)
        atomicAdd(&g_cnt[threadIdx.x], s[threadIdx.x]);
}

__global__ void gdiv_kernel(float* __restrict__ gsum) {
    int i = blockIdx.x * blockDim.x + threadIdx.x;
    if (i < NGRAPH * DOUTC) {
        int g = i / DOUTC;
        gsum[i] = gsum[i] / fmaxf(g_cnt[g], 1.0f);
    }
}

__global__ void logits_kernel(const float* __restrict__ ge, const float* __restrict__ Wc,
                              const float* __restrict__ bc, float* __restrict__ out) {
    int t = threadIdx.x;
    int g = t >> 1, j = t & 1;
    float s = __ldg(&bc[j]);
    #pragma unroll 8
    for (int c = 0; c < DOUTC; ++c)
        s += ge[g * DOUTC + c] * __ldg(&Wc[c * 2 + j]);
    out[t] = s;
}

// ---------------------------------------------------------------------------
// launch
// ---------------------------------------------------------------------------
extern "C" void kernel_launch(void* const* d_in, const int* in_sizes, int n_in,
                              void* d_out, int out_size) {
    const float* x     = (const float*)d_in[0];
    const int*   ei    = (const int*)d_in[1];
    const int*   batch = (const int*)d_in[2];
    const float* W_in  = (const float*)d_in[3];
    const float* b_in  = (const float*)d_in[4];
    const float* W_mid = (const float*)d_in[5];
    const float* b_mid = (const float*)d_in[6];
    const float* W_out = (const float*)d_in[7];
    const float* b_out = (const float*)d_in[8];
    const float* W_cls = (const float*)d_in[9];
    const float* b_cls = (const float*)d_in[10];

    const int* src = ei;
    const int* dst = ei + NEDGES;

    float *bufA, *bufB, *cntp;
    int *cnti;
    __nv_bfloat16 *w1h, *w1l, *w2h, *w2l, *w3h, *w3l;
    cudaGetSymbolAddress((void**)&bufA, g_bufA);
    cudaGetSymbolAddress((void**)&bufB, g_bufB);
    cudaGetSymbolAddress((void**)&cntp, g_cnt);
    cudaGetSymbolAddress((void**)&cnti, g_cnti);
    cudaGetSymbolAddress((void**)&w1h, g_w1_hi);
    cudaGetSymbolAddress((void**)&w1l, g_w1_lo);
    cudaGetSymbolAddress((void**)&w2h, g_w2_hi);
    cudaGetSymbolAddress((void**)&w2l, g_w2_lo);
    cudaGetSymbolAddress((void**)&w3h, g_w3_hi);
    cudaGetSymbolAddress((void**)&w3l, g_w3_lo);

    float* node   = (float*)d_out;
    float* gsum   = node + (size_t)NNODES * DOUTC;
    float* logit  = gsum + NGRAPH * DOUTC;

    const int T = 256;

    // ----- weight prep (transpose + bf16 split) -----
    wprep_kernel<<<(DIN * DH + T - 1) / T, T>>>(W_in, w1h, w1l, DIN, DH);
    wprep_kernel<<<(DH * DH + T - 1) / T, T>>>(W_mid, w2h, w2l, DH, DH);
    wprep_kernel<<<(DH * DOUTC + T - 1) / T, T>>>(W_out, w3h, w3l, DH, DOUTC);

    // ----- CSR build + norm coefficients -----
    zeroi_kernel<<<(NNODES + T - 1) / T, T>>>(cnti, NNODES);
    hist_kernel<<<(NEDGES + T - 1) / T, T>>>(dst, NEDGES);
    dis_kernel<<<(NNODES + T - 1) / T, T>>>(NNODES);
    scan1_kernel<<<SCAN_NB, SCAN_B>>>();
    scan2_kernel<<<1, SCAN_B>>>();
    scan3_kernel<<<SCAN_NB, SCAN_B>>>();
    csrfill_kernel<<<(NEDGES + T - 1) / T, T>>>(src, dst, NEDGES);

    const int GB = (NNODES + 127) / 128;   // 313

    // ----- layer 1: x[N,128] @ W_in[128,256] -----
    mma_gemm_kernel<DIN><<<dim3(2, GB), 512>>>(x, w1h, w1l, bufA, NNODES, DH);
    gather_kernel<DH, true><<<(NNODES * 2 * 32 + T - 1) / T, T>>>(bufA, b_in, bufB);

    // ----- layer 2: h1[N,256] @ W_mid[256,256] -----
    mma_gemm_kernel<DH><<<dim3(2, GB), 512>>>(bufB, w2h, w2l, bufA, NNODES, DH);
    gather_kernel<DH, true><<<(NNODES * 2 * 32 + T - 1) / T, T>>>(bufA, b_mid, bufB);

    // ----- layer 3: h2[N,256] @ W_out[256,128] -----
    mma_gemm_kernel<DH><<<dim3(1, GB), 512>>>(bufB, w3h, w3l, bufA, NNODES, DOUTC);
    gather_kernel<DOUTC, false><<<(NNODES * 1 * 32 + T - 1) / T, T>>>(bufA, b_out, node);

    // ----- mean pool + classifier -----
    fill_kernel<<<8, T>>>((float4*)gsum, 0.0f, NGRAPH * DOUTC / 4);
    fill_kernel<<<1, 16>>>((float4*)cntp, 0.0f, NGRAPH / 4);
    counts_kernel<<<64, T>>>(batch, NNODES);
    pool_kernel<<<(NNODES + 255) / 256, 128>>>(node, batch, gsum, NNODES);
    gdiv_kernel<<<(NGRAPH * DOUTC + T - 1) / T, T>>>(gsum);
    logits_kernel<<<1, 128>>>(gsum, W_cls, b_cls, logit);
}

// round 7
// speedup vs baseline: 1.8711x; 1.1233x over previous
#include <cuda_runtime.h>
#include <cuda_bf16.h>
#include <stdint.h>

#define NNODES 40000
#define NEDGES 640000
#define NGRAPH 64
#define DIN    128
#define DH     256
#define DOUTC  128

#define SCAN_B 256
#define SCAN_NB ((NNODES + SCAN_B - 1) / SCAN_B)   // 157

// ---- scratch (no allocations allowed) ----
__device__ float g_bufA[NNODES * DH];
__device__ float g_bufB[NNODES * DH];
__device__ float g_dis[NNODES];
__device__ float g_cnt[NGRAPH];
// CSR scratch
__device__ int   g_cnti[NNODES];
__device__ int   g_rowptr[NNODES + 1];
__device__ int   g_cursor[NNODES];
__device__ int   g_esrc[NEDGES];
__device__ float g_ecoef[NEDGES];
__device__ int   g_bsum[SCAN_NB];
__device__ int   g_bpre[SCAN_NB];
// weights transposed to [NOUT, K] row-major, bf16 hi/lo split
__device__ __nv_bfloat16 g_w1_hi[DH * DIN];
__device__ __nv_bfloat16 g_w1_lo[DH * DIN];
__device__ __nv_bfloat16 g_w2_hi[DH * DH];
__device__ __nv_bfloat16 g_w2_lo[DH * DH];
__device__ __nv_bfloat16 g_w3_hi[DOUTC * DH];
__device__ __nv_bfloat16 g_w3_lo[DOUTC * DH];

// ---------------------------------------------------------------------------
// small utility kernels
// ---------------------------------------------------------------------------
__global__ void fill_kernel(float4* __restrict__ p, float v, int n4) {
    int i = blockIdx.x * blockDim.x + threadIdx.x;
    float4 f = make_float4(v, v, v, v);
    for (; i < n4; i += gridDim.x * blockDim.x) p[i] = f;
}

__global__ void zeroi_kernel(int* __restrict__ p, int n) {
    int i = blockIdx.x * blockDim.x + threadIdx.x;
    if (i < n) p[i] = 0;
}

__global__ void hist_kernel(const int* __restrict__ dst, int E) {
    int e = blockIdx.x * blockDim.x + threadIdx.x;
    if (e < E) atomicAdd(&g_cnti[dst[e]], 1);
}

__global__ void dis_kernel(int n) {
    int i = blockIdx.x * blockDim.x + threadIdx.x;
    if (i < n) g_dis[i] = rsqrtf((float)g_cnti[i] + 1.0f);
}

// weight prep: W[K, NOUT] fp32 -> transposed [NOUT, K], bf16 hi/lo split
__global__ void wprep_kernel(const float* __restrict__ W, __nv_bfloat16* __restrict__ hi,
                             __nv_bfloat16* __restrict__ lo, int K, int NOUT) {
    int idx = blockIdx.x * blockDim.x + threadIdx.x;
    if (idx >= K * NOUT) return;
    int k = idx / NOUT, n = idx - k * NOUT;
    float v = W[idx];
    __nv_bfloat16 h = __float2bfloat16(v);
    __nv_bfloat16 l = __float2bfloat16(v - __bfloat162float(h));
    hi[(size_t)n * K + k] = h;
    lo[(size_t)n * K + k] = l;
}

// ---------------------------------------------------------------------------
// three-phase scan of g_cnti -> g_rowptr / g_cursor
// ---------------------------------------------------------------------------
__global__ void scan1_kernel() {
    __shared__ int s[SCAN_B];
    int i = blockIdx.x * SCAN_B + threadIdx.x;
    s[threadIdx.x] = (i < NNODES) ? g_cnti[i] : 0;
    __syncthreads();
    for (int off = SCAN_B / 2; off > 0; off >>= 1) {
        if (threadIdx.x < off) s[threadIdx.x] += s[threadIdx.x + off];
        __syncthreads();
    }
    if (threadIdx.x == 0) g_bsum[blockIdx.x] = s[0];
}

__global__ void scan2_kernel() {
    __shared__ int s[SCAN_NB];
    int t = threadIdx.x;
    if (t < SCAN_NB) s[t] = g_bsum[t];
    __syncthreads();
    for (int off = 1; off < SCAN_NB; off <<= 1) {
        int v = 0;
        if (t < SCAN_NB && t >= off) v = s[t - off];
        __syncthreads();
        if (t < SCAN_NB && t >= off) s[t] += v;
        __syncthreads();
    }
    if (t < SCAN_NB) g_bpre[t] = (t == 0) ? 0 : s[t - 1];
    if (t == 0) g_rowptr[NNODES] = NEDGES;
}

__global__ void scan3_kernel() {
    __shared__ int s[SCAN_B];
    int i = blockIdx.x * SCAN_B + threadIdx.x;
    int t = threadIdx.x;
    int v0 = (i < NNODES) ? g_cnti[i] : 0;
    s[t] = v0;
    __syncthreads();
    for (int off = 1; off < SCAN_B; off <<= 1) {
        int v = (t >= off) ? s[t - off] : 0;
        __syncthreads();
        s[t] += v;
        __syncthreads();
    }
    if (i < NNODES) {
        int ex = g_bpre[blockIdx.x] + s[t] - v0;
        g_rowptr[i] = ex;
        g_cursor[i] = ex;
    }
}

__global__ void csrfill_kernel(const int* __restrict__ src, const int* __restrict__ dst,
                               int E) {
    int e = blockIdx.x * blockDim.x + threadIdx.x;
    if (e >= E) return;
    int s = src[e], d = dst[e];
    int p = atomicAdd(&g_cursor[d], 1);
    g_esrc[p]  = s;
    g_ecoef[p] = g_dis[s] * g_dis[d];
}

// ---------------------------------------------------------------------------
// 3xBF16 split GEMM via mma.sync.m16n8k16: C[N, NOUT] = A[N, K] @ W[K, NOUT]
// CTA 512 thr, tile 128x128, K-step 32, warp grid 4x4, warp tile 32x32.
// Software pipeline: prefetch next tile to regs during compute of current.
// Optional fused bias + relu epilogue.
// ---------------------------------------------------------------------------
__device__ __forceinline__ void mma16816(float* c, const uint32_t* a, const uint32_t* b) {
    asm volatile(
        "mma.sync.aligned.m16n8k16.row.col.f32.bf16.bf16.f32 "
        "{%0,%1,%2,%3}, {%4,%5,%6,%7}, {%8,%9}, {%0,%1,%2,%3};"
        : "+f"(c[0]), "+f"(c[1]), "+f"(c[2]), "+f"(c[3])
        : "r"(a[0]), "r"(a[1]), "r"(a[2]), "r"(a[3]), "r"(b[0]), "r"(b[1]));
}

template <int K, bool BRELU>
__global__ void __launch_bounds__(512)
mma_gemm_kernel(const float* __restrict__ A, const __nv_bfloat16* __restrict__ Whi,
                const __nv_bfloat16* __restrict__ Wlo, const float* __restrict__ bias,
                float* __restrict__ C, int N, int NOUT) {
    __shared__ __nv_bfloat16 AsH[128][40];
    __shared__ __nv_bfloat16 AsL[128][40];
    __shared__ __nv_bfloat16 BsH[128][40];
    __shared__ __nv_bfloat16 BsL[128][40];

    const int tid = threadIdx.x;
    const int wid = tid >> 5, lane = tid & 31;
    const int mw = (wid & 3) * 32;
    const int nw = (wid >> 2) * 32;
    const int m0 = blockIdx.y * 128;
    const int n0 = blockIdx.x * 128;

    float acc[2][4][4] = {};
    const int ar = lane >> 2;
    const int ac = (lane & 3) * 2;

    // staging registers
    float2 va[4];
    uint4 vbh, vbl;
    const int br = tid >> 2;             // B row (n-index within tile)
    const int bc = (tid & 3) * 8;        // B col (k within tile)

    auto load_tile = [&](int kt) {
        #pragma unroll
        for (int it = 0; it < 4; ++it) {
            int idx = tid + it * 512;
            int r  = idx >> 4;
            int kp = (idx & 15) * 2;
            int rr = min(m0 + r, N - 1);
            va[it] = *(const float2*)(A + (size_t)rr * K + kt + kp);
        }
        vbh = *(const uint4*)(Whi + (size_t)(n0 + br) * K + kt + bc);
        vbl = *(const uint4*)(Wlo + (size_t)(n0 + br) * K + kt + bc);
    };
    auto store_tile = [&]() {
        #pragma unroll
        for (int it = 0; it < 4; ++it) {
            int idx = tid + it * 512;
            int r  = idx >> 4;
            int kp = (idx & 15) * 2;
            __nv_bfloat16 h0 = __float2bfloat16(va[it].x);
            __nv_bfloat16 h1 = __float2bfloat16(va[it].y);
            __nv_bfloat16 l0 = __float2bfloat16(va[it].x - __bfloat162float(h0));
            __nv_bfloat16 l1 = __float2bfloat16(va[it].y - __bfloat162float(h1));
            *(uint32_t*)&AsH[r][kp] = (uint32_t)__bfloat16_as_ushort(h0) |
                                      ((uint32_t)__bfloat16_as_ushort(h1) << 16);
            *(uint32_t*)&AsL[r][kp] = (uint32_t)__bfloat16_as_ushort(l0) |
                                      ((uint32_t)__bfloat16_as_ushort(l1) << 16);
        }
        *(uint4*)&BsH[br][bc] = vbh;
        *(uint4*)&BsL[br][bc] = vbl;
    };

    load_tile(0);
    store_tile();
    __syncthreads();

    for (int kt = 0; kt < K; kt += 32) {
        const bool more = (kt + 32) < K;
        if (more) load_tile(kt + 32);     // LDG in flight during compute

        #pragma unroll
        for (int k16 = 0; k16 < 32; k16 += 16) {
            uint32_t ah[2][4], al[2][4];
            #pragma unroll
            for (int mt = 0; mt < 2; ++mt) {
                int r = mw + mt * 16 + ar;
                ah[mt][0] = *(uint32_t*)&AsH[r][k16 + ac];
                ah[mt][1] = *(uint32_t*)&AsH[r + 8][k16 + ac];
                ah[mt][2] = *(uint32_t*)&AsH[r][k16 + ac + 8];
                ah[mt][3] = *(uint32_t*)&AsH[r + 8][k16 + ac + 8];
                al[mt][0] = *(uint32_t*)&AsL[r][k16 + ac];
                al[mt][1] = *(uint32_t*)&AsL[r + 8][k16 + ac];
                al[mt][2] = *(uint32_t*)&AsL[r][k16 + ac + 8];
                al[mt][3] = *(uint32_t*)&AsL[r + 8][k16 + ac + 8];
            }
            uint32_t bh[4][2], bl[4][2];
            #pragma unroll
            for (int nt = 0; nt < 4; ++nt) {
                int r = nw + nt * 8 + ar;
                bh[nt][0] = *(uint32_t*)&BsH[r][k16 + ac];
                bh[nt][1] = *(uint32_t*)&BsH[r][k16 + ac + 8];
                bl[nt][0] = *(uint32_t*)&BsL[r][k16 + ac];
                bl[nt][1] = *(uint32_t*)&BsL[r][k16 + ac + 8];
            }
            #pragma unroll
            for (int mt = 0; mt < 2; ++mt)
                #pragma unroll
                for (int nt = 0; nt < 4; ++nt) {
                    mma16816(acc[mt][nt], ah[mt], bh[nt]);
                    mma16816(acc[mt][nt], ah[mt], bl[nt]);
                    mma16816(acc[mt][nt], al[mt], bh[nt]);
                }
        }
        if (more) {
            __syncthreads();    // everyone done reading smem
            store_tile();
            __syncthreads();    // tile visible
        }
    }

    // ---- store (optionally fused bias + relu) ----
    #pragma unroll
    for (int mt = 0; mt < 2; ++mt) {
        int r0 = m0 + mw + mt * 16 + ar;
        #pragma unroll
        for (int nt = 0; nt < 4; ++nt) {
            int c = n0 + nw + nt * 8 + ac;
            float2 o0 = make_float2(acc[mt][nt][0], acc[mt][nt][1]);
            float2 o1 = make_float2(acc[mt][nt][2], acc[mt][nt][3]);
            if (BRELU) {
                float b0 = __ldg(&bias[c]), b1 = __ldg(&bias[c + 1]);
                o0.x = fmaxf(o0.x + b0, 0.f); o0.y = fmaxf(o0.y + b1, 0.f);
                o1.x = fmaxf(o1.x + b0, 0.f); o1.y = fmaxf(o1.y + b1, 0.f);
            }
            if (r0 < N)     *(float2*)(C + (size_t)r0 * NOUT + c) = o0;
            if (r0 + 8 < N) *(float2*)(C + (size_t)(r0 + 8) * NOUT + c) = o1;
        }
    }
}

// ---------------------------------------------------------------------------
// fused gather + self-loop (+bias) (+relu):
//   out[n] = sum coef*h[src] + dis^2*h[n] (+ bias) (relu)
// ---------------------------------------------------------------------------
template <int H, bool RELU, bool BIAS>
__global__ void gather_kernel(const float* __restrict__ h, const float* __restrict__ bias,
                              float* __restrict__ out) {
    constexpr int HALVES = H / 128;
    int w = (blockIdx.x * blockDim.x + threadIdx.x) >> 5;
    int n = w / HALVES;
    if (n >= NNODES) return;
    int half = w - n * HALVES;
    int lane = threadIdx.x & 31;
    int col  = half * 128 + lane * 4;

    int p  = g_rowptr[n];
    int p1 = g_rowptr[n + 1];

    float4 acc = make_float4(0.f, 0.f, 0.f, 0.f);
    for (; p + 3 < p1; p += 4) {
        int   s0 = g_esrc[p],     s1 = g_esrc[p + 1];
        int   s2 = g_esrc[p + 2], s3 = g_esrc[p + 3];
        float c0 = g_ecoef[p],     c1 = g_ecoef[p + 1];
        float c2 = g_ecoef[p + 2], c3 = g_ecoef[p + 3];
        float4 v0 = __ldg((const float4*)(h + (size_t)s0 * H + col));
        float4 v1 = __ldg((const float4*)(h + (size_t)s1 * H + col));
        float4 v2 = __ldg((const float4*)(h + (size_t)s2 * H + col));
        float4 v3 = __ldg((const float4*)(h + (size_t)s3 * H + col));
        acc.x += c0 * v0.x + c1 * v1.x + c2 * v2.x + c3 * v3.x;
        acc.y += c0 * v0.y + c1 * v1.y + c2 * v2.y + c3 * v3.y;
        acc.z += c0 * v0.z + c1 * v1.z + c2 * v2.z + c3 * v3.z;
        acc.w += c0 * v0.w + c1 * v1.w + c2 * v2.w + c3 * v3.w;
    }
    for (; p < p1; ++p) {
        int s = g_esrc[p]; float c = g_ecoef[p];
        float4 v = __ldg((const float4*)(h + (size_t)s * H + col));
        acc.x += c * v.x; acc.y += c * v.y; acc.z += c * v.z; acc.w += c * v.w;
    }

    float dis = g_dis[n];
    float c2 = dis * dis;
    float4 hv = __ldg((const float4*)(h + (size_t)n * H + col));
    float4 r;
    r.x = acc.x + c2 * hv.x;
    r.y = acc.y + c2 * hv.y;
    r.z = acc.z + c2 * hv.z;
    r.w = acc.w + c2 * hv.w;
    if (BIAS) {
        float4 bv = __ldg((const float4*)(bias + col));
        r.x += bv.x; r.y += bv.y; r.z += bv.z; r.w += bv.w;
    }
    if (RELU) {
        r.x = fmaxf(r.x, 0.f); r.y = fmaxf(r.y, 0.f);
        r.z = fmaxf(r.z, 0.f); r.w = fmaxf(r.w, 0.f);
    }
    *(float4*)(out + (size_t)n * H + col) = r;
}

// ---------------------------------------------------------------------------
// pooling + classifier
// ---------------------------------------------------------------------------
__global__ void pool_kernel(const float* __restrict__ ne, const int* __restrict__ batch,
                            float* __restrict__ gsum, int N) {
    int c  = threadIdx.x;
    int n0 = blockIdx.x * 256;
    int n1 = min(n0 + 256, N);
    float acc = 0.0f;
    int cur = -1;
    for (int n = n0; n < n1; ++n) {
        int g = __ldg(&batch[n]);
        if (g != cur) {
            if (cur >= 0) atomicAdd(&gsum[cur * DOUTC + c], acc);
            acc = 0.0f;
            cur = g;
        }
        acc += ne[(size_t)n * DOUTC + c];
    }
    if (cur >= 0) atomicAdd(&gsum[cur * DOUTC + c], acc);
}

__global__ void counts_kernel(const int* __restrict__ batch, int N) {
    __shared__ float s[NGRAPH];
    if (threadIdx.x < NGRAPH) s[threadIdx.x] = 0.0f;
    __syncthreads();
    for (int n = blockIdx.x * blockDim.x + threadIdx.x; n < N;
         n += gridDim.x * blockDim.x)
        atomicAdd(&s[batch[n]], 1.0f);
    __syncthreads();
    if (threadIdx.x < NGRAPH && s[threadIdx.x] > 0.0f)
        atomicAdd(&g_cnt[threadIdx.x], s[threadIdx.x]);
}

__global__ void gdiv_kernel(float* __restrict__ gsum) {
    int i = blockIdx.x * blockDim.x + threadIdx.x;
    if (i < NGRAPH * DOUTC) {
        int g = i / DOUTC;
        gsum[i] = gsum[i] / fmaxf(g_cnt[g], 1.0f);
    }
}

__global__ void logits_kernel(const float* __restrict__ ge, const float* __restrict__ Wc,
                              const float* __restrict__ bc, float* __restrict__ out) {
    int t = threadIdx.x;
    int g = t >> 1, j = t & 1;
    float s = __ldg(&bc[j]);
    #pragma unroll 8
    for (int c = 0; c < DOUTC; ++c)
        s += ge[g * DOUTC + c] * __ldg(&Wc[c * 2 + j]);
    out[t] = s;
}

// ---------------------------------------------------------------------------
// launch
// ---------------------------------------------------------------------------
extern "C" void kernel_launch(void* const* d_in, const int* in_sizes, int n_in,
                              void* d_out, int out_size) {
    const float* x     = (const float*)d_in[0];
    const int*   ei    = (const int*)d_in[1];
    const int*   batch = (const int*)d_in[2];
    const float* W_in  = (const float*)d_in[3];
    const float* b_in  = (const float*)d_in[4];
    const float* W_mid = (const float*)d_in[5];
    const float* b_mid = (const float*)d_in[6];
    const float* W_out = (const float*)d_in[7];
    const float* b_out = (const float*)d_in[8];
    const float* W_cls = (const float*)d_in[9];
    const float* b_cls = (const float*)d_in[10];

    const int* src = ei;
    const int* dst = ei + NEDGES;

    float *bufA, *bufB, *cntp;
    int *cnti;
    __nv_bfloat16 *w1h, *w1l, *w2h, *w2l, *w3h, *w3l;
    cudaGetSymbolAddress((void**)&bufA, g_bufA);
    cudaGetSymbolAddress((void**)&bufB, g_bufB);
    cudaGetSymbolAddress((void**)&cntp, g_cnt);
    cudaGetSymbolAddress((void**)&cnti, g_cnti);
    cudaGetSymbolAddress((void**)&w1h, g_w1_hi);
    cudaGetSymbolAddress((void**)&w1l, g_w1_lo);
    cudaGetSymbolAddress((void**)&w2h, g_w2_hi);
    cudaGetSymbolAddress((void**)&w2l, g_w2_lo);
    cudaGetSymbolAddress((void**)&w3h, g_w3_hi);
    cudaGetSymbolAddress((void**)&w3l, g_w3_lo);

    float* node   = (float*)d_out;
    float* gsum   = node + (size_t)NNODES * DOUTC;
    float* logit  = gsum + NGRAPH * DOUTC;

    const int T = 256;

    // ----- weight prep (transpose + bf16 split) -----
    wprep_kernel<<<(DIN * DH + T - 1) / T, T>>>(W_in, w1h, w1l, DIN, DH);
    wprep_kernel<<<(DH * DH + T - 1) / T, T>>>(W_mid, w2h, w2l, DH, DH);
    wprep_kernel<<<(DH * DOUTC + T - 1) / T, T>>>(W_out, w3h, w3l, DH, DOUTC);

    // ----- CSR build + norm coefficients -----
    zeroi_kernel<<<(NNODES + T - 1) / T, T>>>(cnti, NNODES);
    hist_kernel<<<(NEDGES + T - 1) / T, T>>>(dst, NEDGES);
    dis_kernel<<<(NNODES + T - 1) / T, T>>>(NNODES);
    scan1_kernel<<<SCAN_NB, SCAN_B>>>();
    scan2_kernel<<<1, SCAN_B>>>();
    scan3_kernel<<<SCAN_NB, SCAN_B>>>();
    csrfill_kernel<<<(NEDGES + T - 1) / T, T>>>(src, dst, NEDGES);

    const int GB = (NNODES + 127) / 128;   // 313

    // ----- layer 1: propagate(x) [128-wide], then GEMM + bias + relu -----
    gather_kernel<DIN, false, false><<<(NNODES * 32 + T - 1) / T, T>>>(x, nullptr, bufA);
    mma_gemm_kernel<DIN, true><<<dim3(2, GB), 512>>>(bufA, w1h, w1l, b_in, bufB,
                                                     NNODES, DH);

    // ----- layer 2: GEMM, then propagate + bias + relu -----
    mma_gemm_kernel<DH, false><<<dim3(2, GB), 512>>>(bufB, w2h, w2l, nullptr, bufA,
                                                     NNODES, DH);
    gather_kernel<DH, true, true><<<(NNODES * 2 * 32 + T - 1) / T, T>>>(bufA, b_mid, bufB);

    // ----- layer 3: GEMM, then propagate + bias (no relu) -----
    mma_gemm_kernel<DH, false><<<dim3(1, GB), 512>>>(bufB, w3h, w3l, nullptr, bufA,
                                                     NNODES, DOUTC);
    gather_kernel<DOUTC, false, true><<<(NNODES * 32 + T - 1) / T, T>>>(bufA, b_out, node);

    // ----- mean pool + classifier -----
    fill_kernel<<<8, T>>>((float4*)gsum, 0.0f, NGRAPH * DOUTC / 4);
    fill_kernel<<<1, 16>>>((float4*)cntp, 0.0f, NGRAPH / 4);
    counts_kernel<<<64, T>>>(batch, NNODES);
    pool_kernel<<<(NNODES + 255) / 256, 128>>>(node, batch, gsum, NNODES);
    gdiv_kernel<<<(NGRAPH * DOUTC + T - 1) / T, T>>>(gsum);
    logits_kernel<<<1, 128>>>(gsum, W_cls, b_cls, logit);
}

// round 8
// speedup vs baseline: 2.0160x; 1.0775x over previous
#include <cuda_runtime.h>
#include <cuda_bf16.h>
#include <stdint.h>

#define NNODES 40000
#define NEDGES 640000
#define NGRAPH 64
#define DIN    128
#define DH     256
#define DOUTC  128

#define SCAN_B 256
#define SCAN_NB ((NNODES + SCAN_B - 1) / SCAN_B)   // 157

// ---- scratch (no allocations allowed) ----
__device__ float g_bufA[NNODES * DH];
__device__ float g_bufB[NNODES * DH];
__device__ float g_dis[NNODES];
// CSR scratch
__device__ int   g_cnti[NNODES];
__device__ int   g_rowptr[NNODES + 1];
__device__ int   g_cursor[NNODES];
__device__ int2  g_epack[NEDGES];          // {src, coef-as-int}
__device__ int   g_bsum[SCAN_NB];
__device__ int   g_bpre[SCAN_NB];
// weights transposed to [NOUT, K] row-major, bf16 hi/lo split
__device__ __nv_bfloat16 g_w1_hi[DH * DIN];
__device__ __nv_bfloat16 g_w1_lo[DH * DIN];
__device__ __nv_bfloat16 g_w2_hi[DH * DH];
__device__ __nv_bfloat16 g_w2_lo[DH * DH];
__device__ __nv_bfloat16 g_w3_hi[DOUTC * DH];
__device__ __nv_bfloat16 g_w3_lo[DOUTC * DH];

// ---------------------------------------------------------------------------
// small utility kernels
// ---------------------------------------------------------------------------
__global__ void fill_kernel(float4* __restrict__ p, float v, int n4) {
    int i = blockIdx.x * blockDim.x + threadIdx.x;
    float4 f = make_float4(v, v, v, v);
    for (; i < n4; i += gridDim.x * blockDim.x) p[i] = f;
}

__device__ __forceinline__ void wsplit(const float* __restrict__ W,
                                       __nv_bfloat16* __restrict__ hi,
                                       __nv_bfloat16* __restrict__ lo,
                                       int K, int NOUT, int idx) {
    int k = idx / NOUT, n = idx - k * NOUT;
    float v = W[idx];
    __nv_bfloat16 h = __float2bfloat16(v);
    __nv_bfloat16 l = __float2bfloat16(v - __bfloat162float(h));
    hi[(size_t)n * K + k] = h;
    lo[(size_t)n * K + k] = l;
}

// fused: weight transpose+split for all 3 layers, plus zero of degree counters
__global__ void prep_kernel(const float* __restrict__ W1, const float* __restrict__ W2,
                            const float* __restrict__ W3) {
    constexpr int E1 = DIN * DH;
    constexpr int E2 = E1 + DH * DH;
    constexpr int E3 = E2 + DH * DOUTC;
    constexpr int TOT = E3 + NNODES;
    int i = blockIdx.x * blockDim.x + threadIdx.x;
    for (; i < TOT; i += gridDim.x * blockDim.x) {
        if (i < E1)       wsplit(W1, g_w1_hi, g_w1_lo, DIN, DH, i);
        else if (i < E2)  wsplit(W2, g_w2_hi, g_w2_lo, DH, DH, i - E1);
        else if (i < E3)  wsplit(W3, g_w3_hi, g_w3_lo, DH, DOUTC, i - E2);
        else              g_cnti[i - E3] = 0;
    }
}

__global__ void hist_kernel(const int* __restrict__ dst, int E) {
    int e = blockIdx.x * blockDim.x + threadIdx.x;
    if (e < E) atomicAdd(&g_cnti[dst[e]], 1);
}

// ---------------------------------------------------------------------------
// three-phase scan of g_cnti -> g_rowptr / g_cursor (scan1 also emits dis)
// ---------------------------------------------------------------------------
__global__ void scan1_kernel() {
    __shared__ int s[SCAN_B];
    int i = blockIdx.x * SCAN_B + threadIdx.x;
    int v = (i < NNODES) ? g_cnti[i] : 0;
    if (i < NNODES) g_dis[i] = rsqrtf((float)v + 1.0f);
    s[threadIdx.x] = v;
    __syncthreads();
    for (int off = SCAN_B / 2; off > 0; off >>= 1) {
        if (threadIdx.x < off) s[threadIdx.x] += s[threadIdx.x + off];
        __syncthreads();
    }
    if (threadIdx.x == 0) g_bsum[blockIdx.x] = s[0];
}

__global__ void scan2_kernel() {
    __shared__ int s[SCAN_NB];
    int t = threadIdx.x;
    if (t < SCAN_NB) s[t] = g_bsum[t];
    __syncthreads();
    for (int off = 1; off < SCAN_NB; off <<= 1) {
        int v = 0;
        if (t < SCAN_NB && t >= off) v = s[t - off];
        __syncthreads();
        if (t < SCAN_NB && t >= off) s[t] += v;
        __syncthreads();
    }
    if (t < SCAN_NB) g_bpre[t] = (t == 0) ? 0 : s[t - 1];
    if (t == 0) g_rowptr[NNODES] = NEDGES;
}

__global__ void scan3_kernel() {
    __shared__ int s[SCAN_B];
    int i = blockIdx.x * SCAN_B + threadIdx.x;
    int t = threadIdx.x;
    int v0 = (i < NNODES) ? g_cnti[i] : 0;
    s[t] = v0;
    __syncthreads();
    for (int off = 1; off < SCAN_B; off <<= 1) {
        int v = (t >= off) ? s[t - off] : 0;
        __syncthreads();
        s[t] += v;
        __syncthreads();
    }
    if (i < NNODES) {
        int ex = g_bpre[blockIdx.x] + s[t] - v0;
        g_rowptr[i] = ex;
        g_cursor[i] = ex;
    }
}

__global__ void csrfill_kernel(const int* __restrict__ src, const int* __restrict__ dst,
                               int E) {
    int e = blockIdx.x * blockDim.x + threadIdx.x;
    if (e >= E) return;
    int s = src[e], d = dst[e];
    int p = atomicAdd(&g_cursor[d], 1);
    g_epack[p] = make_int2(s, __float_as_int(g_dis[s] * g_dis[d]));
}

// ---------------------------------------------------------------------------
// 3xBF16 split GEMM via mma.sync.m16n8k16: C[N, NOUT] = A[N, K] @ W[K, NOUT]
// CTA 512 thr, tile 128x128, K-step 32, warp grid 4x4, warp tile 32x32.
// Software pipeline; optional fused bias + relu epilogue.
// ---------------------------------------------------------------------------
__device__ __forceinline__ void mma16816(float* c, const uint32_t* a, const uint32_t* b) {
    asm volatile(
        "mma.sync.aligned.m16n8k16.row.col.f32.bf16.bf16.f32 "
        "{%0,%1,%2,%3}, {%4,%5,%6,%7}, {%8,%9}, {%0,%1,%2,%3};"
        : "+f"(c[0]), "+f"(c[1]), "+f"(c[2]), "+f"(c[3])
        : "r"(a[0]), "r"(a[1]), "r"(a[2]), "r"(a[3]), "r"(b[0]), "r"(b[1]));
}

template <int K, bool BRELU>
__global__ void __launch_bounds__(512)
mma_gemm_kernel(const float* __restrict__ A, const __nv_bfloat16* __restrict__ Whi,
                const __nv_bfloat16* __restrict__ Wlo, const float* __restrict__ bias,
                float* __restrict__ C, int N, int NOUT) {
    __shared__ __nv_bfloat16 AsH[128][40];
    __shared__ __nv_bfloat16 AsL[128][40];
    __shared__ __nv_bfloat16 BsH[128][40];
    __shared__ __nv_bfloat16 BsL[128][40];

    const int tid = threadIdx.x;
    const int wid = tid >> 5, lane = tid & 31;
    const int mw = (wid & 3) * 32;
    const int nw = (wid >> 2) * 32;
    const int m0 = blockIdx.y * 128;
    const int n0 = blockIdx.x * 128;

    float acc[2][4][4] = {};
    const int ar = lane >> 2;
    const int ac = (lane & 3) * 2;

    float2 va[4];
    uint4 vbh, vbl;
    const int br = tid >> 2;
    const int bc = (tid & 3) * 8;

    auto load_tile = [&](int kt) {
        #pragma unroll
        for (int it = 0; it < 4; ++it) {
            int idx = tid + it * 512;
            int r  = idx >> 4;
            int kp = (idx & 15) * 2;
            int rr = min(m0 + r, N - 1);
            va[it] = *(const float2*)(A + (size_t)rr * K + kt + kp);
        }
        vbh = *(const uint4*)(Whi + (size_t)(n0 + br) * K + kt + bc);
        vbl = *(const uint4*)(Wlo + (size_t)(n0 + br) * K + kt + bc);
    };
    auto store_tile = [&]() {
        #pragma unroll
        for (int it = 0; it < 4; ++it) {
            int idx = tid + it * 512;
            int r  = idx >> 4;
            int kp = (idx & 15) * 2;
            __nv_bfloat16 h0 = __float2bfloat16(va[it].x);
            __nv_bfloat16 h1 = __float2bfloat16(va[it].y);
            __nv_bfloat16 l0 = __float2bfloat16(va[it].x - __bfloat162float(h0));
            __nv_bfloat16 l1 = __float2bfloat16(va[it].y - __bfloat162float(h1));
            *(uint32_t*)&AsH[r][kp] = (uint32_t)__bfloat16_as_ushort(h0) |
                                      ((uint32_t)__bfloat16_as_ushort(h1) << 16);
            *(uint32_t*)&AsL[r][kp] = (uint32_t)__bfloat16_as_ushort(l0) |
                                      ((uint32_t)__bfloat16_as_ushort(l1) << 16);
        }
        *(uint4*)&BsH[br][bc] = vbh;
        *(uint4*)&BsL[br][bc] = vbl;
    };

    load_tile(0);
    store_tile();
    __syncthreads();

    for (int kt = 0; kt < K; kt += 32) {
        const bool more = (kt + 32) < K;
        if (more) load_tile(kt + 32);

        #pragma unroll
        for (int k16 = 0; k16 < 32; k16 += 16) {
            uint32_t ah[2][4], al[2][4];
            #pragma unroll
            for (int mt = 0; mt < 2; ++mt) {
                int r = mw + mt * 16 + ar;
                ah[mt][0] = *(uint32_t*)&AsH[r][k16 + ac];
                ah[mt][1] = *(uint32_t*)&AsH[r + 8][k16 + ac];
                ah[mt][2] = *(uint32_t*)&AsH[r][k16 + ac + 8];
                ah[mt][3] = *(uint32_t*)&AsH[r + 8][k16 + ac + 8];
                al[mt][0] = *(uint32_t*)&AsL[r][k16 + ac];
                al[mt][1] = *(uint32_t*)&AsL[r + 8][k16 + ac];
                al[mt][2] = *(uint32_t*)&AsL[r][k16 + ac + 8];
                al[mt][3] = *(uint32_t*)&AsL[r + 8][k16 + ac + 8];
            }
            uint32_t bh[4][2], bl[4][2];
            #pragma unroll
            for (int nt = 0; nt < 4; ++nt) {
                int r = nw + nt * 8 + ar;
                bh[nt][0] = *(uint32_t*)&BsH[r][k16 + ac];
                bh[nt][1] = *(uint32_t*)&BsH[r][k16 + ac + 8];
                bl[nt][0] = *(uint32_t*)&BsL[r][k16 + ac];
                bl[nt][1] = *(uint32_t*)&BsL[r][k16 + ac + 8];
            }
            #pragma unroll
            for (int mt = 0; mt < 2; ++mt)
                #pragma unroll
                for (int nt = 0; nt < 4; ++nt) {
                    mma16816(acc[mt][nt], ah[mt], bh[nt]);
                    mma16816(acc[mt][nt], ah[mt], bl[nt]);
                    mma16816(acc[mt][nt], al[mt], bh[nt]);
                }
        }
        if (more) {
            __syncthreads();
            store_tile();
            __syncthreads();
        }
    }

    #pragma unroll
    for (int mt = 0; mt < 2; ++mt) {
        int r0 = m0 + mw + mt * 16 + ar;
        #pragma unroll
        for (int nt = 0; nt < 4; ++nt) {
            int c = n0 + nw + nt * 8 + ac;
            float2 o0 = make_float2(acc[mt][nt][0], acc[mt][nt][1]);
            float2 o1 = make_float2(acc[mt][nt][2], acc[mt][nt][3]);
            if (BRELU) {
                float b0 = __ldg(&bias[c]), b1 = __ldg(&bias[c + 1]);
                o0.x = fmaxf(o0.x + b0, 0.f); o0.y = fmaxf(o0.y + b1, 0.f);
                o1.x = fmaxf(o1.x + b0, 0.f); o1.y = fmaxf(o1.y + b1, 0.f);
            }
            if (r0 < N)     *(float2*)(C + (size_t)r0 * NOUT + c) = o0;
            if (r0 + 8 < N) *(float2*)(C + (size_t)(r0 + 8) * NOUT + c) = o1;
        }
    }
}

// ---------------------------------------------------------------------------
// fused gather + self-loop (+bias) (+relu), packed edge records
// ---------------------------------------------------------------------------
template <int H, bool RELU, bool BIAS>
__global__ void gather_kernel(const float* __restrict__ h, const float* __restrict__ bias,
                              float* __restrict__ out) {
    constexpr int HALVES = H / 128;
    int w = (blockIdx.x * blockDim.x + threadIdx.x) >> 5;
    int n = w / HALVES;
    if (n >= NNODES) return;
    int half = w - n * HALVES;
    int lane = threadIdx.x & 31;
    int col  = half * 128 + lane * 4;

    int p  = __ldg(&g_rowptr[n]);
    int p1 = __ldg(&g_rowptr[n + 1]);

    float4 acc = make_float4(0.f, 0.f, 0.f, 0.f);
    for (; p + 3 < p1; p += 4) {
        int2 e0 = __ldg(&g_epack[p]);
        int2 e1 = __ldg(&g_epack[p + 1]);
        int2 e2 = __ldg(&g_epack[p + 2]);
        int2 e3 = __ldg(&g_epack[p + 3]);
        float c0 = __int_as_float(e0.y), c1 = __int_as_float(e1.y);
        float c2 = __int_as_float(e2.y), c3 = __int_as_float(e3.y);
        float4 v0 = __ldg((const float4*)(h + (size_t)e0.x * H + col));
        float4 v1 = __ldg((const float4*)(h + (size_t)e1.x * H + col));
        float4 v2 = __ldg((const float4*)(h + (size_t)e2.x * H + col));
        float4 v3 = __ldg((const float4*)(h + (size_t)e3.x * H + col));
        acc.x += c0 * v0.x + c1 * v1.x + c2 * v2.x + c3 * v3.x;
        acc.y += c0 * v0.y + c1 * v1.y + c2 * v2.y + c3 * v3.y;
        acc.z += c0 * v0.z + c1 * v1.z + c2 * v2.z + c3 * v3.z;
        acc.w += c0 * v0.w + c1 * v1.w + c2 * v2.w + c3 * v3.w;
    }
    for (; p < p1; ++p) {
        int2 e = __ldg(&g_epack[p]);
        float c = __int_as_float(e.y);
        float4 v = __ldg((const float4*)(h + (size_t)e.x * H + col));
        acc.x += c * v.x; acc.y += c * v.y; acc.z += c * v.z; acc.w += c * v.w;
    }

    float dis = g_dis[n];
    float c2 = dis * dis;
    float4 hv = __ldg((const float4*)(h + (size_t)n * H + col));
    float4 r;
    r.x = acc.x + c2 * hv.x;
    r.y = acc.y + c2 * hv.y;
    r.z = acc.z + c2 * hv.z;
    r.w = acc.w + c2 * hv.w;
    if (BIAS) {
        float4 bv = __ldg((const float4*)(bias + col));
        r.x += bv.x; r.y += bv.y; r.z += bv.z; r.w += bv.w;
    }
    if (RELU) {
        r.x = fmaxf(r.x, 0.f); r.y = fmaxf(r.y, 0.f);
        r.z = fmaxf(r.z, 0.f); r.w = fmaxf(r.w, 0.f);
    }
    *(float4*)(out + (size_t)n * H + col) = r;
}

// ---------------------------------------------------------------------------
// pooling: batch sorted -> register accumulation, few atomics
// ---------------------------------------------------------------------------
__global__ void pool_kernel(const float* __restrict__ ne, const int* __restrict__ batch,
                            float* __restrict__ gsum, int N) {
    int c  = threadIdx.x;
    int n0 = blockIdx.x * 256;
    int n1 = min(n0 + 256, N);
    float acc = 0.0f;
    int cur = -1;
    for (int n = n0; n < n1; ++n) {
        int g = __ldg(&batch[n]);
        if (g != cur) {
            if (cur >= 0) atomicAdd(&gsum[cur * DOUTC + c], acc);
            acc = 0.0f;
            cur = g;
        }
        acc += ne[(size_t)n * DOUTC + c];
    }
    if (cur >= 0) atomicAdd(&gsum[cur * DOUTC + c], acc);
}

// fused: per-graph count (binary search over sorted batch), mean divide, logits
__global__ void finish_kernel(const int* __restrict__ batch, float* __restrict__ gsum,
                              const float* __restrict__ Wc, const float* __restrict__ bc,
                              float* __restrict__ logit) {
    int g = blockIdx.x;
    __shared__ float cnt_s;
    __shared__ float row[DOUTC];
    if (threadIdx.x == 0) {
        int lo = 0, hi = NNODES;
        while (lo < hi) { int mid = (lo + hi) >> 1; if (__ldg(&batch[mid]) < g) lo = mid + 1; else hi = mid; }
        int lb = lo;
        lo = 0; hi = NNODES;
        while (lo < hi) { int mid = (lo + hi) >> 1; if (__ldg(&batch[mid]) <= g) lo = mid + 1; else hi = mid; }
        cnt_s = fmaxf((float)(lo - lb), 1.0f);
    }
    __syncthreads();
    int c = threadIdx.x;
    float v = gsum[g * DOUTC + c] / cnt_s;
    gsum[g * DOUTC + c] = v;
    row[c] = v;
    __syncthreads();
    if (c < 2) {
        float s = __ldg(&bc[c]);
        #pragma unroll 8
        for (int k = 0; k < DOUTC; ++k) s += row[k] * __ldg(&Wc[k * 2 + c]);
        logit[g * 2 + c] = s;
    }
}

// ---------------------------------------------------------------------------
// launch
// ---------------------------------------------------------------------------
extern "C" void kernel_launch(void* const* d_in, const int* in_sizes, int n_in,
                              void* d_out, int out_size) {
    const float* x     = (const float*)d_in[0];
    const int*   ei    = (const int*)d_in[1];
    const int*   batch = (const int*)d_in[2];
    const float* W_in  = (const float*)d_in[3];
    const float* b_in  = (const float*)d_in[4];
    const float* W_mid = (const float*)d_in[5];
    const float* b_mid = (const float*)d_in[6];
    const float* W_out = (const float*)d_in[7];
    const float* b_out = (const float*)d_in[8];
    const float* W_cls = (const float*)d_in[9];
    const float* b_cls = (const float*)d_in[10];

    const int* src = ei;
    const int* dst = ei + NEDGES;

    float *bufA, *bufB;
    __nv_bfloat16 *w1h, *w1l, *w2h, *w2l, *w3h, *w3l;
    cudaGetSymbolAddress((void**)&bufA, g_bufA);
    cudaGetSymbolAddress((void**)&bufB, g_bufB);
    cudaGetSymbolAddress((void**)&w1h, g_w1_hi);
    cudaGetSymbolAddress((void**)&w1l, g_w1_lo);
    cudaGetSymbolAddress((void**)&w2h, g_w2_hi);
    cudaGetSymbolAddress((void**)&w2l, g_w2_lo);
    cudaGetSymbolAddress((void**)&w3h, g_w3_hi);
    cudaGetSymbolAddress((void**)&w3l, g_w3_lo);

    float* node   = (float*)d_out;
    float* gsum   = node + (size_t)NNODES * DOUTC;
    float* logit  = gsum + NGRAPH * DOUTC;

    const int T = 256;

    // ----- prep (weights + zero counters) and CSR build -----
    prep_kernel<<<680, T>>>(W_in, W_mid, W_out);
    hist_kernel<<<(NEDGES + T - 1) / T, T>>>(dst, NEDGES);
    scan1_kernel<<<SCAN_NB, SCAN_B>>>();
    scan2_kernel<<<1, SCAN_B>>>();
    scan3_kernel<<<SCAN_NB, SCAN_B>>>();
    csrfill_kernel<<<(NEDGES + T - 1) / T, T>>>(src, dst, NEDGES);

    const int GB = (NNODES + 127) / 128;   // 313

    // ----- layer 1: propagate(x) [128-wide], then GEMM + bias + relu -----
    gather_kernel<DIN, false, false><<<(NNODES * 32 + T - 1) / T, T>>>(x, nullptr, bufA);
    mma_gemm_kernel<DIN, true><<<dim3(2, GB), 512>>>(bufA, w1h, w1l, b_in, bufB,
                                                     NNODES, DH);

    // ----- layer 2: GEMM, then propagate + bias + relu -----
    mma_gemm_kernel<DH, false><<<dim3(2, GB), 512>>>(bufB, w2h, w2l, nullptr, bufA,
                                                     NNODES, DH);
    gather_kernel<DH, true, true><<<(NNODES * 2 * 32 + T - 1) / T, T>>>(bufA, b_mid, bufB);

    // ----- layer 3: GEMM, then propagate + bias (no relu) -----
    mma_gemm_kernel<DH, false><<<dim3(1, GB), 512>>>(bufB, w3h, w3l, nullptr, bufA,
                                                     NNODES, DOUTC);
    gather_kernel<DOUTC, false, true><<<(NNODES * 32 + T - 1) / T, T>>>(bufA, b_out, node);

    // ----- mean pool + classifier -----
    fill_kernel<<<8, T>>>((float4*)gsum, 0.0f, NGRAPH * DOUTC / 4);
    pool_kernel<<<(NNODES + 255) / 256, 128>>>(node, batch, gsum, NNODES);
    finish_kernel<<<NGRAPH, DOUTC>>>(batch, gsum, W_cls, b_cls, logit);
}